// round 1
// baseline (speedup 1.0000x reference)
#include <cuda_runtime.h>
#include <cuda_bf16.h>
#include <math.h>

// Problem constants
#define V_  5
#define B_  1
#define C_  32
#define H_  384
#define W_  384
#define D_  4
#define G_  8
#define HW_ (H_ * W_)          // 147456
#define CPG (C_ / G_)          // 4

// Scratch: transposed features (V, H*W, C) for contiguous per-pixel channel reads.
__device__ float g_featT[(size_t)V_ * HW_ * C_];   // ~94.4 MB
// Camera precompute: Kinv0[9], Rinv0[9], t0[3]
__device__ float g_kinv[9];
__device__ float g_rinv[9];
__device__ float g_t0[3];

__device__ __forceinline__ void invert3(const float* m, float* inv) {
    float a = m[0], b = m[1], c = m[2];
    float d = m[3], e = m[4], f = m[5];
    float g = m[6], h = m[7], i = m[8];
    float A =  (e*i - f*h);
    float Bc = -(d*i - f*g);
    float Cc =  (d*h - e*g);
    float det = a*A + b*Bc + c*Cc;
    float id = 1.0f / det;
    inv[0] = A * id;
    inv[1] = -(b*i - c*h) * id;
    inv[2] =  (b*f - c*e) * id;
    inv[3] = Bc * id;
    inv[4] =  (a*i - c*g) * id;
    inv[5] = -(a*f - c*d) * id;
    inv[6] = Cc * id;
    inv[7] = -(a*h - b*g) * id;
    inv[8] =  (a*e - b*d) * id;
}

__global__ void setup_cams_kernel(const float* __restrict__ K,
                                  const float* __restrict__ E) {
    if (threadIdx.x == 0 && blockIdx.x == 0) {
        // K[0] is cam_intrinsic[0,0] (3x3), E[0] is cam_extrinsic[0,0] (3x4)
        invert3(K, g_kinv);
        float R0[9];
        #pragma unroll
        for (int i = 0; i < 3; i++)
            #pragma unroll
            for (int j = 0; j < 3; j++)
                R0[i*3 + j] = E[i*4 + j];
        invert3(R0, g_rinv);
        #pragma unroll
        for (int i = 0; i < 3; i++) g_t0[i] = E[i*4 + 3];
    }
}

// CHW -> HWC transpose per view. block (32,32), grid (HW/32, V)
__global__ void transpose_kernel(const float* __restrict__ f) {
    __shared__ float s[32][33];
    int v  = blockIdx.y;
    int p0 = blockIdx.x * 32;
    int tx = threadIdx.x, ty = threadIdx.y;
    // read f[v][c=ty][p0+tx] : coalesced in p
    s[ty][tx] = f[((size_t)v * C_ + ty) * HW_ + p0 + tx];
    __syncthreads();
    // write g_featT[v][p0+ty][c=tx] : coalesced in c
    g_featT[(size_t)v * HW_ * C_ + (size_t)(p0 + ty) * C_ + tx] = s[tx][ty];
}

__global__ void __launch_bounds__(256)
gbinet_main_kernel(const float* __restrict__ depths,
                   const float* __restrict__ Kall,
                   const float* __restrict__ Eall,
                   const float* __restrict__ w0, const float* __restrict__ b0,
                   const float* __restrict__ w1, const float* __restrict__ b1,
                   const float* __restrict__ w2, const float* __restrict__ b2,
                   float* __restrict__ out) {
    __shared__ float sw0[16*8], sb0[16], sw1[8*16], sb1[8], sw2[8], sb2;
    __shared__ float sKinv[9], sRinv[9], st0[3];
    __shared__ float sK[4][9], sR[4][9], st[4][3];

    int tid = threadIdx.x;
    for (int i = tid; i < 128; i += 256) sw0[i] = w0[i];
    for (int i = tid; i < 128; i += 256) sw1[i] = w1[i];
    if (tid < 16) sb0[tid] = b0[tid];
    if (tid < 8)  sb1[tid] = b1[tid];
    if (tid < 8)  sw2[tid] = w2[tid];
    if (tid == 0) sb2 = b2[0];
    if (tid < 9)  sKinv[tid] = g_kinv[tid];
    if (tid < 9)  sRinv[tid] = g_rinv[tid];
    if (tid < 3)  st0[tid] = g_t0[tid];
    // source views 1..4 -> slots 0..3
    if (tid >= 32 && tid < 32 + 4*9) {
        int i = tid - 32; int s = i / 9; int j = i % 9;
        sK[s][j] = Kall[(s + 1) * 9 + j];
        sR[s][j] = Eall[(s + 1) * 12 + (j / 3) * 4 + (j % 3)];
    }
    if (tid >= 96 && tid < 96 + 12) {
        int i = tid - 96; int s = i / 3; int j = i % 3;
        st[s][j] = Eall[(s + 1) * 12 + j * 4 + 3];
    }
    __syncthreads();

    int pix = blockIdx.x * 256 + tid;   // HW divisible by 256
    int y = pix / W_;
    int x = pix - y * W_;
    float gx = (float)x + 0.5f;
    float gy = (float)y + 0.5f;

    // uv = Kinv @ (gx, gy, 1)
    float u0 = sKinv[0]*gx + sKinv[1]*gy + sKinv[2];
    float u1 = sKinv[3]*gx + sKinv[4]*gy + sKinv[5];
    float u2 = sKinv[6]*gx + sKinv[7]*gy + sKinv[8];

    float dep[D_];
    #pragma unroll
    for (int d = 0; d < D_; d++) dep[d] = depths[d * HW_ + pix];

    const float4* __restrict__ fT4 = (const float4*)g_featT;

    // ref features (view 0), 8 groups x float4
    float4 ref[G_];
    #pragma unroll
    for (int g = 0; g < G_; g++) ref[g] = fT4[(size_t)pix * 8 + g];

    // world points per depth
    float wxp[D_], wyp[D_], wzp[D_];
    #pragma unroll
    for (int d = 0; d < D_; d++) {
        float cx = u0 * dep[d] - st0[0];
        float cy = u1 * dep[d] - st0[1];
        float cz = u2 * dep[d] - st0[2];
        wxp[d] = sRinv[0]*cx + sRinv[1]*cy + sRinv[2]*cz;
        wyp[d] = sRinv[3]*cx + sRinv[4]*cy + sRinv[5]*cz;
        wzp[d] = sRinv[6]*cx + sRinv[7]*cy + sRinv[8]*cz;
    }

    float simsum[D_ * G_];
    #pragma unroll
    for (int i = 0; i < D_ * G_; i++) simsum[i] = 0.0f;
    float wsum = 0.0f;

    for (int s = 0; s < 4; s++) {
        float sim[D_ * G_];
        const size_t vbase = (size_t)(s + 1) * HW_;

        #pragma unroll
        for (int d = 0; d < D_; d++) {
            // cp = R_s @ world + t_s
            float cpx = sR[s][0]*wxp[d] + sR[s][1]*wyp[d] + sR[s][2]*wzp[d] + st[s][0];
            float cpy = sR[s][3]*wxp[d] + sR[s][4]*wyp[d] + sR[s][5]*wzp[d] + st[s][1];
            float cpz = sR[s][6]*wxp[d] + sR[s][7]*wyp[d] + sR[s][8]*wzp[d] + st[s][2];
            // uvd = K_s @ cp
            float uh = sK[s][0]*cpx + sK[s][1]*cpy + sK[s][2]*cpz;
            float vh = sK[s][3]*cpx + sK[s][4]*cpy + sK[s][5]*cpz;
            float zh = sK[s][6]*cpx + sK[s][7]*cpy + sK[s][8]*cpz;
            float z  = zh + 1e-9f;
            float px = uh / z;
            float py = vh / z;

            float x0f = floorf(px);
            float y0f = floorf(py);
            float wx1 = px - x0f, wx0v = 1.0f - wx1;
            float wy1 = py - y0f, wy0v = 1.0f - wy1;

            float acc[G_];
            #pragma unroll
            for (int g = 0; g < G_; g++) acc[g] = 0.0f;

            #pragma unroll
            for (int corner = 0; corner < 4; corner++) {
                float xf = x0f + (float)(corner & 1);
                float yf = y0f + (float)(corner >> 1);
                float w  = ((corner & 1) ? wx1 : wx0v) * ((corner >> 1) ? wy1 : wy0v);
                if (xf >= 0.0f && xf <= (float)(W_ - 1) &&
                    yf >= 0.0f && yf <= (float)(H_ - 1)) {
                    int xi = (int)xf;
                    int yi = (int)yf;
                    const float4* p = fT4 + (vbase + (size_t)yi * W_ + xi) * 8;
                    #pragma unroll
                    for (int g = 0; g < G_; g++) {
                        float4 f = __ldg(p + g);
                        float4 r = ref[g];
                        float dot = f.x*r.x + f.y*r.y + f.z*r.z + f.w*r.w;
                        acc[g] = fmaf(w, dot, acc[g]);
                    }
                }
            }
            #pragma unroll
            for (int g = 0; g < G_; g++) sim[d * G_ + g] = 0.25f * acc[g];
        }

        // pixelwise net: vw = max_d sigmoid(MLP(sim[d,:]))
        float vw = 0.0f;
        #pragma unroll
        for (int d = 0; d < D_; d++) {
            float x0v[16];
            #pragma unroll
            for (int o = 0; o < 16; o++) {
                float t = sb0[o];
                #pragma unroll
                for (int g = 0; g < G_; g++) t = fmaf(sw0[o*8 + g], sim[d*G_ + g], t);
                x0v[o] = fmaxf(t, 0.0f);
            }
            float x1v[8];
            #pragma unroll
            for (int j = 0; j < 8; j++) {
                float t = sb1[j];
                #pragma unroll
                for (int o = 0; o < 16; o++) t = fmaf(sw1[j*16 + o], x0v[o], t);
                x1v[j] = fmaxf(t, 0.0f);
            }
            float yv = sb2;
            #pragma unroll
            for (int j = 0; j < 8; j++) yv = fmaf(sw2[j], x1v[j], yv);
            float sg = 1.0f / (1.0f + expf(-yv));
            vw = fmaxf(vw, sg);
        }

        #pragma unroll
        for (int i = 0; i < D_ * G_; i++) simsum[i] = fmaf(sim[i], vw, simsum[i]);
        wsum += vw;
    }

    float invw = 1.0f / wsum;
    #pragma unroll
    for (int g = 0; g < G_; g++)
        #pragma unroll
        for (int d = 0; d < D_; d++)
            out[(size_t)(g * D_ + d) * HW_ + pix] = simsum[d * G_ + g] * invw;
}

extern "C" void kernel_launch(void* const* d_in, const int* in_sizes, int n_in,
                              void* d_out, int out_size) {
    const float* features = (const float*)d_in[0];  // (5,1,32,384,384)
    const float* depths   = (const float*)d_in[1];  // (1,4,384,384)
    const float* Kall     = (const float*)d_in[2];  // (1,5,3,3)
    const float* Eall     = (const float*)d_in[3];  // (1,5,3,4)
    const float* w0 = (const float*)d_in[4];
    const float* b0 = (const float*)d_in[5];
    const float* w1 = (const float*)d_in[6];
    const float* b1 = (const float*)d_in[7];
    const float* w2 = (const float*)d_in[8];
    const float* b2 = (const float*)d_in[9];
    float* out = (float*)d_out;
    (void)in_sizes; (void)n_in; (void)out_size;

    setup_cams_kernel<<<1, 32>>>(Kall, Eall);

    dim3 tb(32, 32);
    dim3 tg(HW_ / 32, V_);
    transpose_kernel<<<tg, tb>>>(features);

    gbinet_main_kernel<<<HW_ / 256, 256>>>(depths, Kall, Eall,
                                           w0, b0, w1, b1, w2, b2, out);
}

// round 2
// speedup vs baseline: 2.0296x; 2.0296x over previous
#include <cuda_runtime.h>
#include <cuda_bf16.h>
#include <math.h>

#define V_  5
#define C_  32
#define H_  384
#define W_  384
#define D_  4
#define G_  8
#define HW_ (H_ * W_)          // 147456

// Transposed features (V, H*W, C): per-pixel channels contiguous.
__device__ float g_featT[(size_t)V_ * HW_ * C_];   // ~94.4 MB
// Folded projection per source view: uvd = M_s * (gx,gy,1) * dep + c_s
__device__ float g_M[4][9];
__device__ float g_c[4][3];

__device__ __forceinline__ void invert3d(const double* m, double* inv) {
    double a = m[0], b = m[1], c = m[2];
    double d = m[3], e = m[4], f = m[5];
    double g = m[6], h = m[7], i = m[8];
    double A  =  (e*i - f*h);
    double Bc = -(d*i - f*g);
    double Cc =  (d*h - e*g);
    double det = a*A + b*Bc + c*Cc;
    double id = 1.0 / det;
    inv[0] = A * id;
    inv[1] = -(b*i - c*h) * id;
    inv[2] =  (b*f - c*e) * id;
    inv[3] = Bc * id;
    inv[4] =  (a*i - c*g) * id;
    inv[5] = -(a*f - c*d) * id;
    inv[6] = Cc * id;
    inv[7] = -(a*h - b*g) * id;
    inv[8] =  (a*e - b*d) * id;
}

__device__ __forceinline__ void mat3mul(const double* A, const double* B, double* Cm) {
    #pragma unroll
    for (int i = 0; i < 3; i++)
        #pragma unroll
        for (int j = 0; j < 3; j++)
            Cm[i*3+j] = A[i*3+0]*B[0*3+j] + A[i*3+1]*B[1*3+j] + A[i*3+2]*B[2*3+j];
}

__global__ void setup_cams_kernel(const float* __restrict__ K,
                                  const float* __restrict__ E) {
    if (threadIdx.x != 0 || blockIdx.x != 0) return;
    double K0[9], Kinv[9], R0[9], Rinv[9], t0[3];
    #pragma unroll
    for (int i = 0; i < 9; i++) K0[i] = (double)K[i];
    invert3d(K0, Kinv);
    #pragma unroll
    for (int i = 0; i < 3; i++) {
        #pragma unroll
        for (int j = 0; j < 3; j++) R0[i*3+j] = (double)E[i*4+j];
        t0[i] = (double)E[i*4+3];
    }
    invert3d(R0, Rinv);

    for (int s = 0; s < 4; s++) {
        double Ks[9], Rs[9], ts[3];
        #pragma unroll
        for (int i = 0; i < 9; i++) Ks[i] = (double)K[(s+1)*9 + i];
        #pragma unroll
        for (int i = 0; i < 3; i++) {
            #pragma unroll
            for (int j = 0; j < 3; j++) Rs[i*3+j] = (double)E[(s+1)*12 + i*4 + j];
            ts[i] = (double)E[(s+1)*12 + i*4 + 3];
        }
        double A[9], B[9], M[9];
        mat3mul(Rs, Rinv, A);    // Rs * Rinv
        mat3mul(Ks, A, B);       // Ks * Rs * Rinv
        mat3mul(B, Kinv, M);     // Ks * Rs * Rinv * Kinv
        // c = Ks*ts - (Ks*Rs*Rinv)*t0
        double c0[3];
        #pragma unroll
        for (int i = 0; i < 3; i++) {
            double kt = Ks[i*3+0]*ts[0] + Ks[i*3+1]*ts[1] + Ks[i*3+2]*ts[2];
            double bt = B[i*3+0]*t0[0] + B[i*3+1]*t0[1] + B[i*3+2]*t0[2];
            c0[i] = kt - bt;
        }
        #pragma unroll
        for (int i = 0; i < 9; i++) g_M[s][i] = (float)M[i];
        #pragma unroll
        for (int i = 0; i < 3; i++) g_c[s][i] = (float)c0[i];
    }
}

// CHW -> HWC transpose per view. block (32,32), grid (HW/32, V)
__global__ void transpose_kernel(const float* __restrict__ f) {
    __shared__ float s[32][33];
    int v  = blockIdx.y;
    int p0 = blockIdx.x * 32;
    int tx = threadIdx.x, ty = threadIdx.y;
    s[ty][tx] = f[((size_t)v * C_ + ty) * HW_ + p0 + tx];
    __syncthreads();
    g_featT[(size_t)v * HW_ * C_ + (size_t)(p0 + ty) * C_ + tx] = s[tx][ty];
}

// Main kernel: 256 threads = 32 pixels x 8 group-lanes.
__global__ void __launch_bounds__(256)
gbinet_main_kernel(const float* __restrict__ depths,
                   const float* __restrict__ w0, const float* __restrict__ b0,
                   const float* __restrict__ w1, const float* __restrict__ b1,
                   const float* __restrict__ w2, const float* __restrict__ b2,
                   float* __restrict__ out) {
    __shared__ float sw0[16*8], sb0[16], sw1[8*16], sb1[8], sw2[8], sb2v[1];
    __shared__ float sM[4][9], sc[4][3];
    __shared__ float ssim[4 * 4 * 32 * 8];   // [s][d][pixL][g] = 16 KB
    __shared__ float svw[4 * 32];            // [s][pixL]

    const int tid  = threadIdx.x;
    const int pixL = tid >> 3;
    const int g    = tid & 7;

    if (tid < 128) sw0[tid] = w0[tid];
    else           sw1[tid - 128] = w1[tid - 128];
    if (tid < 16) sb0[tid] = b0[tid];
    if (tid >= 16 && tid < 24) sb1[tid - 16] = b1[tid - 16];
    if (tid >= 24 && tid < 32) sw2[tid - 24] = w2[tid - 24];
    if (tid == 32) sb2v[0] = b2[0];
    if (tid >= 64 && tid < 64 + 36) {
        int i = tid - 64; sM[i / 9][i % 9] = g_M[i / 9][i % 9];
    }
    if (tid >= 100 && tid < 112) {
        int i = tid - 100; sc[i / 3][i % 3] = g_c[i / 3][i % 3];
    }

    const int pix = blockIdx.x * 32 + pixL;
    const int y = pix / W_;
    const int x = pix - y * W_;
    const float gx = (float)x + 0.5f;
    const float gy = (float)y + 0.5f;

    float dep[D_];
    #pragma unroll
    for (int d = 0; d < D_; d++) dep[d] = depths[d * HW_ + pix];

    const float4* __restrict__ fT4 = (const float4*)g_featT;
    const float4 ref = fT4[(size_t)pix * 8 + g];

    __syncthreads();   // weights + M/c visible

    // ---- gather phase: sim[s][d] for this lane's group ----
    #pragma unroll
    for (int s = 0; s < 4; s++) {
        const float mx = sM[s][0]*gx + sM[s][1]*gy + sM[s][2];
        const float my = sM[s][3]*gx + sM[s][4]*gy + sM[s][5];
        const float mz = sM[s][6]*gx + sM[s][7]*gy + sM[s][8];
        const size_t vbase = (size_t)(s + 1) * HW_;
        #pragma unroll
        for (int d = 0; d < D_; d++) {
            const float uh = fmaf(mx, dep[d], sc[s][0]);
            const float vh = fmaf(my, dep[d], sc[s][1]);
            const float zh = fmaf(mz, dep[d], sc[s][2]);
            const float z  = zh + 1e-9f;
            const float px = uh / z;
            const float py = vh / z;

            const float x0f = floorf(px);
            const float y0f = floorf(py);
            const float wx1 = px - x0f, wx0v = 1.0f - wx1;
            const float wy1 = py - y0f, wy0v = 1.0f - wy1;

            float acc = 0.0f;
            #pragma unroll
            for (int corner = 0; corner < 4; corner++) {
                const float xf = x0f + (float)(corner & 1);
                const float yf = y0f + (float)(corner >> 1);
                const float w = ((corner & 1) ? wx1 : wx0v) *
                                ((corner >> 1) ? wy1 : wy0v);
                if (xf >= 0.0f && xf <= (float)(W_ - 1) &&
                    yf >= 0.0f && yf <= (float)(H_ - 1)) {
                    const int xi = (int)xf;
                    const int yi = (int)yf;
                    const float4 f = __ldg(fT4 + (vbase + (size_t)yi * W_ + xi) * 8 + g);
                    const float dot = f.x*ref.x + f.y*ref.y + f.z*ref.z + f.w*ref.w;
                    acc = fmaf(w, dot, acc);
                }
            }
            ssim[((s * 4 + d) * 32 + pixL) * 8 + g] = 0.25f * acc;
        }
    }
    __syncthreads();

    // ---- MLP phase: 512 (s,pix,d) items over 256 threads, 2 each ----
    #pragma unroll
    for (int it = 0; it < 2; it++) {
        const int i  = tid + it * 256;
        const int s  = i >> 7;
        const int pp = (i >> 2) & 31;
        const int d  = i & 3;
        const int base = ((s * 4 + d) * 32 + pp) * 8;
        float sv[8];
        #pragma unroll
        for (int k = 0; k < 8; k++) sv[k] = ssim[base + k];

        float x0v[16];
        #pragma unroll
        for (int o = 0; o < 16; o++) {
            float t = sb0[o];
            #pragma unroll
            for (int k = 0; k < 8; k++) t = fmaf(sw0[o*8 + k], sv[k], t);
            x0v[o] = fmaxf(t, 0.0f);
        }
        float x1v[8];
        #pragma unroll
        for (int j = 0; j < 8; j++) {
            float t = sb1[j];
            #pragma unroll
            for (int o = 0; o < 16; o++) t = fmaf(sw1[j*16 + o], x0v[o], t);
            x1v[j] = fmaxf(t, 0.0f);
        }
        float yv = sb2v[0];
        #pragma unroll
        for (int j = 0; j < 8; j++) yv = fmaf(sw2[j], x1v[j], yv);
        float val = 1.0f / (1.0f + expf(-yv));

        // max over the 4 depths (quad of consecutive threads)
        val = fmaxf(val, __shfl_xor_sync(0xffffffffu, val, 1));
        val = fmaxf(val, __shfl_xor_sync(0xffffffffu, val, 2));
        if (d == 0) svw[s * 32 + pp] = val;
    }
    __syncthreads();

    // ---- accumulate + output ----
    float simsum[D_] = {0.0f, 0.0f, 0.0f, 0.0f};
    float wsum = 0.0f;
    #pragma unroll
    for (int s = 0; s < 4; s++) {
        const float vw = svw[s * 32 + pixL];
        wsum += vw;
        #pragma unroll
        for (int d = 0; d < D_; d++)
            simsum[d] = fmaf(ssim[((s * 4 + d) * 32 + pixL) * 8 + g], vw, simsum[d]);
    }
    const float invw = 1.0f / wsum;
    #pragma unroll
    for (int d = 0; d < D_; d++)
        out[(size_t)(g * D_ + d) * HW_ + pix] = simsum[d] * invw;
}

extern "C" void kernel_launch(void* const* d_in, const int* in_sizes, int n_in,
                              void* d_out, int out_size) {
    const float* features = (const float*)d_in[0];  // (5,1,32,384,384)
    const float* depths   = (const float*)d_in[1];  // (1,4,384,384)
    const float* Kall     = (const float*)d_in[2];  // (1,5,3,3)
    const float* Eall     = (const float*)d_in[3];  // (1,5,3,4)
    const float* w0 = (const float*)d_in[4];
    const float* b0 = (const float*)d_in[5];
    const float* w1 = (const float*)d_in[6];
    const float* b1 = (const float*)d_in[7];
    const float* w2 = (const float*)d_in[8];
    const float* b2 = (const float*)d_in[9];
    float* out = (float*)d_out;
    (void)in_sizes; (void)n_in; (void)out_size;

    setup_cams_kernel<<<1, 32>>>(Kall, Eall);

    dim3 tb(32, 32);
    dim3 tg(HW_ / 32, V_);
    transpose_kernel<<<tg, tb>>>(features);

    gbinet_main_kernel<<<HW_ / 32, 256>>>(depths, w0, b0, w1, b1, w2, b2, out);
}